// round 13
// baseline (speedup 1.0000x reference)
#include <cuda_runtime.h>
#include <cuda_fp16.h>
#include <cstdint>

// ---------------- problem shapes ----------------
#define B_IMG   64
#define H_IMG   256
#define W_IMG   256
#define PATCH   16
#define ROWS    16384
#define VROWS   4096
#define KDIM    256
#define N_PATCH_ELEMS (ROWS * KDIM)
#define N_TOKENS      ROWS

// ---------------- main GEMM tiling (int8, K-chunk = 128 elems = 128B) ----------------
#define M_CTA   128
#define N_TILE  256
#define NT_COUNT (VROWS / N_TILE)          // 16
#define NKC     2                          // two 128-elem K chunks
#define NCHUNKS (NT_COUNT * NKC)           // 32
#define NTHR    512
#define TH_GAP  1.4f                       // int8 quantization margin

// ---------------- refine1 (single fp16 term, fp32 accum) ----------------
#define REF_SLICES  32
#define REF_VS      (VROWS / REF_SLICES)    // 128
#define REF1_MTILES 48
#define REF1_GRID   (REF1_MTILES * REF_SLICES)  // 1536
#define TH_GAP2     0.05f
// refine1 SMEM
#define R1A    0            // 4 panels x 8KB (64 rows x 128B)
#define R1B    32768        // 128 rows x 128B
#define R1RED  49152
#define R1SMEM 57344

// ---------------- refine2 (3-term fp16 split, near exact) ----------------
#define REF2_MTILES 8
#define REF2_GRID   (REF2_MTILES * REF_SLICES)  // 256
#define TH_GAP3     0.0015f
// refine2 SMEM
#define RA_HI   0
#define RA_LO   32768
#define RB_HI   65536
#define RB_LO   81920
#define RRED    98304
#define RSMEM   106496

// ---------------- exact fixup geometry (tiny cnt3) ----------------
#define FIX_SLABS   32
#define FIX_VSLAB   (VROWS / FIX_SLABS)     // 128
#define FIX_RPG     8
#define FIX_GROUPS  8
#define FIX_GRID    (FIX_SLABS * FIX_GROUPS)   // 256

// ---------------- main GEMM SMEM ----------------
#define SM_A    0            // 2 panels x 16KB
#define SM_B    32768        // 2 bufs x 32KB
#define SM_NHV  98304        // 16KB
#define SM_SV   114688       // 16KB
#define SMEM_BYTES 131072

// ---------------- device scratch ----------------
__device__ float              g_patches[N_PATCH_ELEMS];
__device__ __half             g_ph[N_PATCH_ELEMS];
__device__ __half             g_plo[N_PATCH_ELEMS];
__device__ signed char        g_qp[N_PATCH_ELEMS];
__device__ float              g_sx[ROWS];
__device__ __half             g_vh[VROWS * KDIM];
__device__ __half             g_vlo[VROWS * KDIM];
__device__ signed char        g_qv[VROWS * KDIM];
__device__ float              g_sv[VROWS];
__device__ float              g_nhv2[VROWS];          // -0.5*||v||^2
__device__ int                g_fixcnt, g_fixcnt2, g_fixcnt3;
__device__ int                g_fixlist[ROWS];
__device__ int                g_fixlist2[ROWS];
__device__ int                g_fixlist3[ROWS];
__device__ unsigned long long g_keys[ROWS];
__device__ float4             g_part[ROWS * REF_SLICES];

// ---------------- helpers ----------------
__device__ __forceinline__ uint32_t smem_u32(const void* p) {
    uint32_t a;
    asm("{ .reg .u64 t; cvta.to.shared.u64 t, %1; cvt.u32.u64 %0, t; }" : "=r"(a) : "l"(p));
    return a;
}
#define SMEM_SWZ(off) ((uint32_t)(off) ^ (((uint32_t)(off) >> 3) & 0x70u))

__device__ __forceinline__ void ldm4(uint32_t* r, uint32_t addr) {
    asm volatile("ldmatrix.sync.aligned.m8n8.x4.shared.b16 {%0,%1,%2,%3}, [%4];"
        : "=r"(r[0]), "=r"(r[1]), "=r"(r[2]), "=r"(r[3]) : "r"(addr));
}
__device__ __forceinline__ void mma_f16(float* c, const uint32_t* a, uint32_t b0, uint32_t b1) {
    asm volatile("mma.sync.aligned.m16n8k16.row.col.f32.f16.f16.f32 "
        "{%0,%1,%2,%3}, {%4,%5,%6,%7}, {%8,%9}, {%0,%1,%2,%3};"
        : "+f"(c[0]), "+f"(c[1]), "+f"(c[2]), "+f"(c[3])
        : "r"(a[0]), "r"(a[1]), "r"(a[2]), "r"(a[3]), "r"(b0), "r"(b1));
}
__device__ __forceinline__ void mma_s8(int* c, const uint32_t* a, uint32_t b0, uint32_t b1) {
    asm volatile("mma.sync.aligned.m16n8k32.row.col.s32.s8.s8.s32 "
        "{%0,%1,%2,%3}, {%4,%5,%6,%7}, {%8,%9}, {%0,%1,%2,%3};"
        : "+r"(c[0]), "+r"(c[1]), "+r"(c[2]), "+r"(c[3])
        : "r"(a[0]), "r"(a[1]), "r"(a[2]), "r"(a[3]), "r"(b0), "r"(b1));
}
#define CP16(dst, src)  asm volatile("cp.async.cg.shared.global [%0], [%1], 16;" :: "r"(dst), "l"(src))
#define CP_COMMIT()     asm volatile("cp.async.commit_group;" ::: "memory")
#define CP_WAIT(n)      asm volatile("cp.async.wait_group %0;" :: "n"(n) : "memory")

__device__ __forceinline__ uint32_t pack2h(__half a, __half b) {
    return (uint32_t)__half_as_ushort(a) | ((uint32_t)__half_as_ushort(b) << 16);
}
__device__ __forceinline__ uint32_t ford(float s) {
    uint32_t b = __float_as_uint(s);
    return (b & 0x80000000u) ? ~b : (b | 0x80000000u);
}
__device__ __forceinline__ unsigned long long mkkey(float s, int idx) {
    return ((unsigned long long)ford(s) << 32) | (uint32_t)(~(uint32_t)idx);
}

// ---------------------------------------------------------------------------
// Kernel 1: patchify + fp16 hi/lo split (+ counter reset)
// ---------------------------------------------------------------------------
__global__ void patchify_kernel(const float* __restrict__ img,
                                float* __restrict__ out_opt) {
    int i = blockIdx.x * blockDim.x + threadIdx.x;
    if (blockIdx.x == 0 && threadIdx.x == 0) { g_fixcnt = 0; g_fixcnt2 = 0; g_fixcnt3 = 0; }
    if (i >= N_PATCH_ELEMS / 4) return;
    int f  = i << 2;
    int d  = f & 255;
    int pn = f >> 8;
    int b  = pn >> 8;
    int n  = pn & 255;
    int r  = d >> 4, c = d & 15;
    int py = n >> 4, px = n & 15;
    const float4 v = *(const float4*)(img + (size_t)b * (H_IMG * W_IMG)
                                      + (size_t)(py * PATCH + r) * W_IMG + px * PATCH + c);
    ((float4*)g_patches)[i] = v;
    if (out_opt) ((float4*)out_opt)[i] = v;
    float x[4] = {v.x, v.y, v.z, v.w};
    __half hi[4], lo[4];
    #pragma unroll
    for (int j = 0; j < 4; j++) {
        hi[j] = __float2half_rn(x[j]);
        lo[j] = __float2half_rn(x[j] - __half2float(hi[j]));
    }
    uint2 ph, pl;
    ph.x = pack2h(hi[0], hi[1]); ph.y = pack2h(hi[2], hi[3]);
    pl.x = pack2h(lo[0], lo[1]); pl.y = pack2h(lo[2], lo[3]);
    ((uint2*)g_ph)[i]  = ph;
    ((uint2*)g_plo)[i] = pl;
}

// ---------------------------------------------------------------------------
// Kernel 1b: per-row absmax int8 quantization of patches (1 warp / row)
// ---------------------------------------------------------------------------
__global__ void patch_quant_kernel() {
    const int gt   = blockIdx.x * blockDim.x + threadIdx.x;
    const int row  = gt >> 5;
    const int lane = gt & 31;
    if (row >= ROWS) return;
    const float* src = g_patches + (size_t)row * KDIM + lane * 8;
    float4 q0 = *(const float4*)src;
    float4 q1 = *(const float4*)(src + 4);
    float m = fmaxf(fmaxf(fmaxf(fabsf(q0.x), fabsf(q0.y)), fmaxf(fabsf(q0.z), fabsf(q0.w))),
                    fmaxf(fmaxf(fabsf(q1.x), fabsf(q1.y)), fmaxf(fabsf(q1.z), fabsf(q1.w))));
    #pragma unroll
    for (int off = 16; off; off >>= 1) m = fmaxf(m, __shfl_xor_sync(0xFFFFFFFFu, m, off));
    const float inv = (m > 0.f) ? 127.f / m : 0.f;
    int r[8];
    r[0] = __float2int_rn(q0.x * inv); r[1] = __float2int_rn(q0.y * inv);
    r[2] = __float2int_rn(q0.z * inv); r[3] = __float2int_rn(q0.w * inv);
    r[4] = __float2int_rn(q1.x * inv); r[5] = __float2int_rn(q1.y * inv);
    r[6] = __float2int_rn(q1.z * inv); r[7] = __float2int_rn(q1.w * inv);
    uint2 p;
    p.x = (uint32_t)(uint8_t)r[0] | ((uint32_t)(uint8_t)r[1] << 8)
        | ((uint32_t)(uint8_t)r[2] << 16) | ((uint32_t)(uint8_t)r[3] << 24);
    p.y = (uint32_t)(uint8_t)r[4] | ((uint32_t)(uint8_t)r[5] << 8)
        | ((uint32_t)(uint8_t)r[6] << 16) | ((uint32_t)(uint8_t)r[7] << 24);
    *(uint2*)(g_qp + (size_t)row * KDIM + lane * 8) = p;
    if (lane == 0) g_sx[row] = m / 127.f;
}

// ---------------------------------------------------------------------------
// Kernel 2: vocab prep — -0.5||v||^2 + fp16 hi/lo split (1 warp / row)
// ---------------------------------------------------------------------------
__global__ void vocab_prep_kernel(const float* __restrict__ vocab) {
    int gt   = blockIdx.x * blockDim.x + threadIdx.x;
    int w    = gt >> 5;
    int lane = gt & 31;
    if (w >= VROWS) return;
    float s = 0.f;
    #pragma unroll
    for (int j = 0; j < 2; j++) {
        int e = lane * 4 + j * 128;
        float4 q = *(const float4*)(vocab + (size_t)w * KDIM + e);
        s += q.x * q.x + q.y * q.y + q.z * q.z + q.w * q.w;
        float x[4] = {q.x, q.y, q.z, q.w};
        __half hi[4], lo[4];
        #pragma unroll
        for (int t = 0; t < 4; t++) {
            hi[t] = __float2half_rn(x[t]);
            lo[t] = __float2half_rn(x[t] - __half2float(hi[t]));
        }
        uint2 ph, pl;
        ph.x = pack2h(hi[0], hi[1]); ph.y = pack2h(hi[2], hi[3]);
        pl.x = pack2h(lo[0], lo[1]); pl.y = pack2h(lo[2], lo[3]);
        *(uint2*)(g_vh  + (size_t)w * KDIM + e) = ph;
        *(uint2*)(g_vlo + (size_t)w * KDIM + e) = pl;
    }
    #pragma unroll
    for (int off = 16; off; off >>= 1) s += __shfl_xor_sync(0xFFFFFFFFu, s, off);
    if (lane == 0) g_nhv2[w] = -0.5f * s;
}

// ---------------------------------------------------------------------------
// Kernel 2b: per-row absmax int8 quantization of vocab (1 warp / row)
// ---------------------------------------------------------------------------
__global__ void vocab_quant_kernel(const float* __restrict__ vocab) {
    const int gt   = blockIdx.x * blockDim.x + threadIdx.x;
    const int row  = gt >> 5;
    const int lane = gt & 31;
    if (row >= VROWS) return;
    const float* src = vocab + (size_t)row * KDIM + lane * 8;
    float4 q0 = *(const float4*)src;
    float4 q1 = *(const float4*)(src + 4);
    float m = fmaxf(fmaxf(fmaxf(fabsf(q0.x), fabsf(q0.y)), fmaxf(fabsf(q0.z), fabsf(q0.w))),
                    fmaxf(fmaxf(fabsf(q1.x), fabsf(q1.y)), fmaxf(fabsf(q1.z), fabsf(q1.w))));
    #pragma unroll
    for (int off = 16; off; off >>= 1) m = fmaxf(m, __shfl_xor_sync(0xFFFFFFFFu, m, off));
    const float inv = (m > 0.f) ? 127.f / m : 0.f;
    int r[8];
    r[0] = __float2int_rn(q0.x * inv); r[1] = __float2int_rn(q0.y * inv);
    r[2] = __float2int_rn(q0.z * inv); r[3] = __float2int_rn(q0.w * inv);
    r[4] = __float2int_rn(q1.x * inv); r[5] = __float2int_rn(q1.y * inv);
    r[6] = __float2int_rn(q1.z * inv); r[7] = __float2int_rn(q1.w * inv);
    uint2 p;
    p.x = (uint32_t)(uint8_t)r[0] | ((uint32_t)(uint8_t)r[1] << 8)
        | ((uint32_t)(uint8_t)r[2] << 16) | ((uint32_t)(uint8_t)r[3] << 24);
    p.y = (uint32_t)(uint8_t)r[4] | ((uint32_t)(uint8_t)r[5] << 8)
        | ((uint32_t)(uint8_t)r[6] << 16) | ((uint32_t)(uint8_t)r[7] << 24);
    *(uint2*)(g_qv + (size_t)row * KDIM + lane * 8) = p;
    if (lane == 0) g_sv[row] = m / 127.f;
}

// ---------------------------------------------------------------------------
// Kernel 3: main GEMM — int8 IMMA m16n8k32 + fused top-2 argmax
// 512 thr, 16 warps = 2(M) x 8(N); warp tile 64x32; K-chunk 128 elems.
// ---------------------------------------------------------------------------
__global__ void __launch_bounds__(NTHR, 1)
gemm_imma_kernel(float* __restrict__ tok_f, int* __restrict__ tok_i) {
    extern __shared__ char smem[];
    const uint32_t sb = smem_u32(smem);
    const int t    = threadIdx.x;
    const int wid  = t >> 5;
    const int lane = t & 31;
    const int wm   = wid >> 3;
    const int wn   = wid & 7;
    const int grp  = lane >> 2;
    const int tig  = lane & 3;
    const int m0   = blockIdx.x * M_CTA;

    for (int i = t; i < VROWS / 4; i += NTHR) {
        ((float4*)(smem + SM_NHV))[i] = ((const float4*)g_nhv2)[i];
        ((float4*)(smem + SM_SV))[i]  = ((const float4*)g_sv)[i];
    }

    // A tile: 128 rows x 256 int8, 2 panels of 128B rows, SW128
    #pragma unroll
    for (int i = 0; i < 4; i++) {
        int f = t + i * NTHR;          // 0..2047
        int m = f >> 4;                // row
        int c = f & 15;                // 16B chunk: panel*8 + q
        int panel = c >> 3;
        int q = c & 7;
        uint32_t dst = SMEM_SWZ(m * 128 + q * 16);
        *(uint4*)(smem + SM_A + panel * 16384 + dst) =
            *(const uint4*)(g_qp + (size_t)(m0 + m) * KDIM + panel * 128 + q * 16);
    }
    __syncthreads();

    // per-thread row scales (8 rows handled by this thread)
    float sx8[8];
    #pragma unroll
    for (int mt = 0; mt < 4; mt++) {
        sx8[mt * 2 + 0] = g_sx[m0 + wm * 64 + mt * 16 + grp];
        sx8[mt * 2 + 1] = g_sx[m0 + wm * 64 + mt * 16 + grp + 8];
    }

    // prologue: chunk 0 (nt=0, kc=0): 256 rows x 128B
    #pragma unroll
    for (int i = 0; i < 4; i++) {
        int f = t + i * NTHR;
        int r = f >> 3, q = f & 7;
        uint32_t dst = sb + SM_B + SMEM_SWZ(r * 128 + q * 16);
        CP16(dst, g_qv + (size_t)r * KDIM + q * 16);
    }
    CP_COMMIT();

    int acc[4][4][4];
    #pragma unroll
    for (int a = 0; a < 4; a++)
        #pragma unroll
        for (int b = 0; b < 4; b++)
            #pragma unroll
            for (int c = 0; c < 4; c++) acc[a][b][c] = 0;

    float b1v[8], b2v[8];
    int   i1v[8];
    #pragma unroll
    for (int r = 0; r < 8; r++) { b1v[r] = -3.4e38f; b2v[r] = -3.4e38f; i1v[r] = 0; }

    const float* nhv = (const float*)(smem + SM_NHV);
    const float* svs = (const float*)(smem + SM_SV);

    for (int gch = 0; gch < NCHUNKS; gch++) {
        const int nt  = gch >> 1;
        const int kc  = gch & 1;
        const int buf = gch & 1;

        if (gch < NCHUNKS - 1) {
            const int gn  = gch + 1;
            const int nn0 = (gn >> 1) << 8;
            const int nkc = gn & 1;
            const uint32_t bb = sb + SM_B + (gn & 1) * 32768;
            #pragma unroll
            for (int i = 0; i < 4; i++) {
                int f = t + i * NTHR;
                int r = f >> 3, q = f & 7;
                uint32_t dst = bb + SMEM_SWZ(r * 128 + q * 16);
                CP16(dst, g_qv + (size_t)(nn0 + r) * KDIM + nkc * 128 + q * 16);
            }
            CP_COMMIT();
            CP_WAIT(1);
        } else {
            CP_WAIT(0);
        }
        __syncthreads();

        const uint32_t b_base = sb + SM_B + buf * 32768;
        const uint32_t a_base = sb + SM_A + kc * 16384;
        const int rowA = wm * 64 + (lane & 15);
        const int rowB = wn * 32 + (lane & 15);

        #pragma unroll
        for (int ks = 0; ks < 4; ks++) {            // K=32 int8 per step
            const uint32_t colb = ks * 32 + (lane >> 4) * 16;
            uint32_t ah[4][4], bh[2][4];
            #pragma unroll
            for (int mt = 0; mt < 4; mt++)
                ldm4(ah[mt], a_base + SMEM_SWZ((rowA + mt * 16) * 128 + colb));
            #pragma unroll
            for (int p = 0; p < 2; p++)
                ldm4(bh[p], b_base + SMEM_SWZ((rowB + p * 16) * 128 + colb));
            #pragma unroll
            for (int mt = 0; mt < 4; mt++) {
                #pragma unroll
                for (int n8 = 0; n8 < 4; n8++) {
                    const int p = n8 >> 1, w = n8 & 1;
                    mma_s8(acc[mt][n8], ah[mt],
                           w ? bh[p][1] : bh[p][0],
                           w ? bh[p][3] : bh[p][2]);
                }
            }
        }
        __syncthreads();

        if (kc == 1) {
            #pragma unroll
            for (int mt = 0; mt < 4; mt++) {
                const float sx0 = sx8[mt * 2], sx1 = sx8[mt * 2 + 1];
                #pragma unroll
                for (int n8 = 0; n8 < 4; n8++) {
                    const int cb = nt * N_TILE + wn * 32 + n8 * 8 + tig * 2;
                    const float2 h  = *(const float2*)(nhv + cb);
                    const float2 sv = *(const float2*)(svs + cb);
                    const float s00 = sx0 * sv.x * (float)acc[mt][n8][0] + h.x;
                    const float s01 = sx0 * sv.y * (float)acc[mt][n8][1] + h.y;
                    const float s10 = sx1 * sv.x * (float)acc[mt][n8][2] + h.x;
                    const float s11 = sx1 * sv.y * (float)acc[mt][n8][3] + h.y;
                    const int r0 = mt * 2, r1 = mt * 2 + 1;
                    if (s00 > b1v[r0]) { b2v[r0] = b1v[r0]; b1v[r0] = s00; i1v[r0] = cb; }
                    else if (s00 > b2v[r0]) b2v[r0] = s00;
                    if (s01 > b1v[r0]) { b2v[r0] = b1v[r0]; b1v[r0] = s01; i1v[r0] = cb + 1; }
                    else if (s01 > b2v[r0]) b2v[r0] = s01;
                    if (s10 > b1v[r1]) { b2v[r1] = b1v[r1]; b1v[r1] = s10; i1v[r1] = cb; }
                    else if (s10 > b2v[r1]) b2v[r1] = s10;
                    if (s11 > b1v[r1]) { b2v[r1] = b1v[r1]; b1v[r1] = s11; i1v[r1] = cb + 1; }
                    else if (s11 > b2v[r1]) b2v[r1] = s11;
                    acc[mt][n8][0] = 0; acc[mt][n8][1] = 0;
                    acc[mt][n8][2] = 0; acc[mt][n8][3] = 0;
                }
            }
        }
    }

    // cross-lane merge (xor lane bits 0,1)
    #pragma unroll
    for (int d = 1; d <= 2; d <<= 1) {
        #pragma unroll
        for (int r = 0; r < 8; r++) {
            float ob1 = __shfl_xor_sync(0xFFFFFFFFu, b1v[r], d);
            float ob2 = __shfl_xor_sync(0xFFFFFFFFu, b2v[r], d);
            int   oi1 = __shfl_xor_sync(0xFFFFFFFFu, i1v[r], d);
            if (ob1 > b1v[r] || (ob1 == b1v[r] && oi1 < i1v[r])) {
                b2v[r] = fmaxf(b1v[r], ob2);
                b1v[r] = ob1; i1v[r] = oi1;
            } else {
                b2v[r] = fmaxf(b2v[r], ob1);
            }
        }
    }

    __syncthreads();
    float4* red = (float4*)(smem + SM_B);
    if (tig == 0) {
        #pragma unroll
        for (int mt = 0; mt < 4; mt++) {
            #pragma unroll
            for (int h = 0; h < 2; h++) {
                const int rl = wm * 64 + mt * 16 + grp + h * 8;
                const int r  = mt * 2 + h;
                red[wn * 128 + rl] = make_float4(b1v[r], b2v[r], __int_as_float(i1v[r]), 0.f);
            }
        }
    }
    __syncthreads();
    if (t < M_CTA) {
        float bb1 = -3.4e38f, bb2 = -3.4e38f;
        int   bi  = 0x7FFFFFFF;
        #pragma unroll
        for (int w = 0; w < 8; w++) {
            float4 e = red[w * 128 + t];
            float ob1 = e.x, ob2 = e.y;
            int   oi1 = __float_as_int(e.z);
            if (ob1 > bb1 || (ob1 == bb1 && oi1 < bi)) {
                bb2 = fmaxf(bb1, ob2); bb1 = ob1; bi = oi1;
            } else {
                bb2 = fmaxf(bb2, ob1);
            }
        }
        const int row = m0 + t;
        if (tok_f) tok_f[row] = (float)bi;
        if (tok_i) tok_i[row] = bi;
        if (bb1 - bb2 < TH_GAP) {
            int pos = atomicAdd(&g_fixcnt, 1);
            g_fixlist[pos] = row;
        }
    }
}

// ---------------------------------------------------------------------------
// Kernel 4: refine1 — single-term fp16 HMMA (fp32 accum) rescore of flagged.
// grid = 48 row-tiles(64) x 32 vocab slices(128). 256 thr.
// ---------------------------------------------------------------------------
__global__ void __launch_bounds__(256, 1)
refine1_kernel() {
    extern __shared__ char smem[];
    const uint32_t sb = smem_u32(smem);
    const int cnt = g_fixcnt;
    if (cnt == 0) return;
    const int t     = threadIdx.x;
    const int wn    = t >> 5;
    const int lane  = t & 31;
    const int grp   = lane >> 2;
    const int tig   = lane & 3;
    const int slice = blockIdx.x & (REF_SLICES - 1);
    const int n0    = slice * REF_VS;

    for (int mt64 = blockIdx.x >> 5; mt64 * 64 < cnt; mt64 += REF1_MTILES) {
        const int base = mt64 * 64;
        __syncthreads();
        for (int i = t; i < 2048; i += 256) {
            int r = i >> 5, c = i & 31;
            int panel = c >> 3, q = c & 7;
            int slot = base + r;
            int grow = g_fixlist[slot < cnt ? slot : base];
            uint32_t dst = panel * 8192 + SMEM_SWZ(r * 128 + q * 16);
            *(uint4*)(smem + R1A + dst) = *(const uint4*)(g_ph + (size_t)grow * KDIM + c * 8);
        }
        __syncthreads();

        float acc[4][2][4];
        #pragma unroll
        for (int a = 0; a < 4; a++)
            #pragma unroll
            for (int b = 0; b < 2; b++)
                #pragma unroll
                for (int c = 0; c < 4; c++) acc[a][b][c] = 0.f;

        for (int kc = 0; kc < 4; kc++) {
            __syncthreads();
            for (int i = t; i < 1024; i += 256) {
                int r = i >> 3, q = i & 7;
                uint32_t dst = SMEM_SWZ(r * 128 + q * 16);
                *(uint4*)(smem + R1B + dst) =
                    *(const uint4*)(g_vh + (size_t)(n0 + r) * KDIM + kc * 64 + q * 8);
            }
            __syncthreads();

            const uint32_t ahb = sb + R1A + kc * 8192;
            const int rowA = lane & 15;
            const int rowB = wn * 16 + (lane & 15);
            #pragma unroll
            for (int ks = 0; ks < 4; ks++) {
                const uint32_t colb = ks * 32 + (lane >> 4) * 16;
                uint32_t ahi[4][4], bhi[4];
                #pragma unroll
                for (int mt = 0; mt < 4; mt++)
                    ldm4(ahi[mt], ahb + SMEM_SWZ((rowA + mt * 16) * 128 + colb));
                ldm4(bhi, sb + R1B + SMEM_SWZ(rowB * 128 + colb));
                #pragma unroll
                for (int mt = 0; mt < 4; mt++) {
                    #pragma unroll
                    for (int n8 = 0; n8 < 2; n8++) {
                        mma_f16(acc[mt][n8], ahi[mt],
                                n8 ? bhi[1] : bhi[0],
                                n8 ? bhi[3] : bhi[2]);
                    }
                }
            }
        }

        float b1v[8], b2v[8];
        int   i1v[8];
        #pragma unroll
        for (int r = 0; r < 8; r++) { b1v[r] = -3.4e38f; b2v[r] = -3.4e38f; i1v[r] = 0; }
        #pragma unroll
        for (int mt = 0; mt < 4; mt++) {
            #pragma unroll
            for (int n8 = 0; n8 < 2; n8++) {
                const int cb = n0 + wn * 16 + n8 * 8 + tig * 2;
                const float hx = g_nhv2[cb], hy = g_nhv2[cb + 1];
                const float s00 = acc[mt][n8][0] + hx;
                const float s01 = acc[mt][n8][1] + hy;
                const float s10 = acc[mt][n8][2] + hx;
                const float s11 = acc[mt][n8][3] + hy;
                const int r0 = mt * 2, r1 = mt * 2 + 1;
                if (s00 > b1v[r0]) { b2v[r0] = b1v[r0]; b1v[r0] = s00; i1v[r0] = cb; }
                else if (s00 > b2v[r0]) b2v[r0] = s00;
                if (s01 > b1v[r0]) { b2v[r0] = b1v[r0]; b1v[r0] = s01; i1v[r0] = cb + 1; }
                else if (s01 > b2v[r0]) b2v[r0] = s01;
                if (s10 > b1v[r1]) { b2v[r1] = b1v[r1]; b1v[r1] = s10; i1v[r1] = cb; }
                else if (s10 > b2v[r1]) b2v[r1] = s10;
                if (s11 > b1v[r1]) { b2v[r1] = b1v[r1]; b1v[r1] = s11; i1v[r1] = cb + 1; }
                else if (s11 > b2v[r1]) b2v[r1] = s11;
            }
        }
        #pragma unroll
        for (int d = 1; d <= 2; d <<= 1) {
            #pragma unroll
            for (int r = 0; r < 8; r++) {
                float ob1 = __shfl_xor_sync(0xFFFFFFFFu, b1v[r], d);
                float ob2 = __shfl_xor_sync(0xFFFFFFFFu, b2v[r], d);
                int   oi1 = __shfl_xor_sync(0xFFFFFFFFu, i1v[r], d);
                if (ob1 > b1v[r] || (ob1 == b1v[r] && oi1 < i1v[r])) {
                    b2v[r] = fmaxf(b1v[r], ob2);
                    b1v[r] = ob1; i1v[r] = oi1;
                } else {
                    b2v[r] = fmaxf(b2v[r], ob1);
                }
            }
        }
        __syncthreads();
        float4* red = (float4*)(smem + R1RED);
        if (tig == 0) {
            #pragma unroll
            for (int mt = 0; mt < 4; mt++) {
                #pragma unroll
                for (int h = 0; h < 2; h++) {
                    const int rl = mt * 16 + grp + h * 8;
                    const int r  = mt * 2 + h;
                    red[wn * 64 + rl] = make_float4(b1v[r], b2v[r], __int_as_float(i1v[r]), 0.f);
                }
            }
        }
        __syncthreads();
        if (t < 64) {
            float bb1 = -3.4e38f, bb2 = -3.4e38f;
            int   bi  = 0x7FFFFFFF;
            #pragma unroll
            for (int w = 0; w < 8; w++) {
                float4 e = red[w * 64 + t];
                float ob1 = e.x, ob2 = e.y;
                int   oi1 = __float_as_int(e.z);
                if (ob1 > bb1 || (ob1 == bb1 && oi1 < bi)) {
                    bb2 = fmaxf(bb1, ob2); bb1 = ob1; bi = oi1;
                } else {
                    bb2 = fmaxf(bb2, ob1);
                }
            }
            g_part[(size_t)(base + t) * REF_SLICES + slice] =
                make_float4(bb1, bb2, __int_as_float(bi), 0.f);
        }
    }
}

// ---------------------------------------------------------------------------
// Kernel 5: merge1 — refine1 slices -> token or refine2 list
// ---------------------------------------------------------------------------
__global__ void __launch_bounds__(256)
merge1_kernel(float* __restrict__ tok_f, int* __restrict__ tok_i) {
    const int i = blockIdx.x * blockDim.x + threadIdx.x;
    if (i >= g_fixcnt) return;
    float bb1 = -3.4e38f, bb2 = -3.4e38f;
    int   bi  = 0x7FFFFFFF;
    #pragma unroll 4
    for (int s = 0; s < REF_SLICES; s++) {
        float4 e = g_part[(size_t)i * REF_SLICES + s];
        float ob1 = e.x, ob2 = e.y;
        int   oi1 = __float_as_int(e.z);
        if (ob1 > bb1 || (ob1 == bb1 && oi1 < bi)) {
            bb2 = fmaxf(bb1, ob2); bb1 = ob1; bi = oi1;
        } else {
            bb2 = fmaxf(bb2, ob1);
        }
    }
    const int row = g_fixlist[i];
    if (bb1 - bb2 < TH_GAP2) {
        int pos = atomicAdd(&g_fixcnt2, 1);
        g_fixlist2[pos] = row;
    } else {
        if (tok_f) tok_f[row] = (float)bi;
        if (tok_i) tok_i[row] = bi;
    }
}

// ---------------------------------------------------------------------------
// Kernel 6: refine2 — 3-term fp16-split HMMA (near exact) on refine2 list
// ---------------------------------------------------------------------------
__global__ void __launch_bounds__(256, 1)
refine2_kernel() {
    extern __shared__ char smem[];
    const uint32_t sb = smem_u32(smem);
    const int cnt = g_fixcnt2;
    if (cnt == 0) return;
    const int t     = threadIdx.x;
    const int wn    = t >> 5;
    const int lane  = t & 31;
    const int grp   = lane >> 2;
    const int tig   = lane & 3;
    const int slice = blockIdx.x & (REF_SLICES - 1);
    const int n0    = slice * REF_VS;

    for (int mt64 = blockIdx.x >> 5; mt64 * 64 < cnt; mt64 += REF2_MTILES) {
        const int base = mt64 * 64;
        __syncthreads();
        for (int i = t; i < 2048; i += 256) {
            int r = i >> 5, c = i & 31;
            int panel = c >> 3, q = c & 7;
            int slot = base + r;
            int grow = g_fixlist2[slot < cnt ? slot : base];
            uint32_t dst = panel * 8192 + SMEM_SWZ(r * 128 + q * 16);
            *(uint4*)(smem + RA_HI + dst) = *(const uint4*)(g_ph  + (size_t)grow * KDIM + c * 8);
            *(uint4*)(smem + RA_LO + dst) = *(const uint4*)(g_plo + (size_t)grow * KDIM + c * 8);
        }
        __syncthreads();

        float acc[4][2][4];
        #pragma unroll
        for (int a = 0; a < 4; a++)
            #pragma unroll
            for (int b = 0; b < 2; b++)
                #pragma unroll
                for (int c = 0; c < 4; c++) acc[a][b][c] = 0.f;

        for (int kc = 0; kc < 4; kc++) {
            __syncthreads();
            for (int i = t; i < 1024; i += 256) {
                int r = i >> 3, q = i & 7;
                uint32_t dst = SMEM_SWZ(r * 128 + q * 16);
                size_t src = (size_t)(n0 + r) * KDIM + kc * 64 + q * 8;
                *(uint4*)(smem + RB_HI + dst) = *(const uint4*)(g_vh  + src);
                *(uint4*)(smem + RB_LO + dst) = *(const uint4*)(g_vlo + src);
            }
            __syncthreads();

            const uint32_t ahb = sb + RA_HI + kc * 8192;
            const uint32_t alb = sb + RA_LO + kc * 8192;
            const int rowA = lane & 15;
            const int rowB = wn * 16 + (lane & 15);
            #pragma unroll
            for (int ks = 0; ks < 4; ks++) {
                const uint32_t colb = ks * 32 + (lane >> 4) * 16;
                uint32_t ahi[4][4], alo[4][4], bhi[4], blo[4];
                #pragma unroll
                for (int mt = 0; mt < 4; mt++) {
                    ldm4(ahi[mt], ahb + SMEM_SWZ((rowA + mt * 16) * 128 + colb));
                    ldm4(alo[mt], alb + SMEM_SWZ((rowA + mt * 16) * 128 + colb));
                }
                ldm4(bhi, sb + RB_HI + SMEM_SWZ(rowB * 128 + colb));
                ldm4(blo, sb + RB_LO + SMEM_SWZ(rowB * 128 + colb));
                #pragma unroll
                for (int mt = 0; mt < 4; mt++) {
                    #pragma unroll
                    for (int n8 = 0; n8 < 2; n8++) {
                        const uint32_t h0 = n8 ? bhi[1] : bhi[0];
                        const uint32_t h1 = n8 ? bhi[3] : bhi[2];
                        const uint32_t l0 = n8 ? blo[1] : blo[0];
                        const uint32_t l1 = n8 ? blo[3] : blo[2];
                        mma_f16(acc[mt][n8], ahi[mt], h0, h1);
                        mma_f16(acc[mt][n8], ahi[mt], l0, l1);
                        mma_f16(acc[mt][n8], alo[mt], h0, h1);
                    }
                }
            }
        }

        float b1v[8], b2v[8];
        int   i1v[8];
        #pragma unroll
        for (int r = 0; r < 8; r++) { b1v[r] = -3.4e38f; b2v[r] = -3.4e38f; i1v[r] = 0; }
        #pragma unroll
        for (int mt = 0; mt < 4; mt++) {
            #pragma unroll
            for (int n8 = 0; n8 < 2; n8++) {
                const int cb = n0 + wn * 16 + n8 * 8 + tig * 2;
                const float hx = g_nhv2[cb], hy = g_nhv2[cb + 1];
                const float s00 = acc[mt][n8][0] + hx;
                const float s01 = acc[mt][n8][1] + hy;
                const float s10 = acc[mt][n8][2] + hx;
                const float s11 = acc[mt][n8][3] + hy;
                const int r0 = mt * 2, r1 = mt * 2 + 1;
                if (s00 > b1v[r0]) { b2v[r0] = b1v[r0]; b1v[r0] = s00; i1v[r0] = cb; }
                else if (s00 > b2v[r0]) b2v[r0] = s00;
                if (s01 > b1v[r0]) { b2v[r0] = b1v[r0]; b1v[r0] = s01; i1v[r0] = cb + 1; }
                else if (s01 > b2v[r0]) b2v[r0] = s01;
                if (s10 > b1v[r1]) { b2v[r1] = b1v[r1]; b1v[r1] = s10; i1v[r1] = cb; }
                else if (s10 > b2v[r1]) b2v[r1] = s10;
                if (s11 > b1v[r1]) { b2v[r1] = b1v[r1]; b1v[r1] = s11; i1v[r1] = cb + 1; }
                else if (s11 > b2v[r1]) b2v[r1] = s11;
            }
        }
        #pragma unroll
        for (int d = 1; d <= 2; d <<= 1) {
            #pragma unroll
            for (int r = 0; r < 8; r++) {
                float ob1 = __shfl_xor_sync(0xFFFFFFFFu, b1v[r], d);
                float ob2 = __shfl_xor_sync(0xFFFFFFFFu, b2v[r], d);
                int   oi1 = __shfl_xor_sync(0xFFFFFFFFu, i1v[r], d);
                if (ob1 > b1v[r] || (ob1 == b1v[r] && oi1 < i1v[r])) {
                    b2v[r] = fmaxf(b1v[r], ob2);
                    b1v[r] = ob1; i1v[r] = oi1;
                } else {
                    b2v[r] = fmaxf(b2v[r], ob1);
                }
            }
        }
        __syncthreads();
        float4* red = (float4*)(smem + RRED);
        if (tig == 0) {
            #pragma unroll
            for (int mt = 0; mt < 4; mt++) {
                #pragma unroll
                for (int h = 0; h < 2; h++) {
                    const int rl = mt * 16 + grp + h * 8;
                    const int r  = mt * 2 + h;
                    red[wn * 64 + rl] = make_float4(b1v[r], b2v[r], __int_as_float(i1v[r]), 0.f);
                }
            }
        }
        __syncthreads();
        if (t < 64) {
            float bb1 = -3.4e38f, bb2 = -3.4e38f;
            int   bi  = 0x7FFFFFFF;
            #pragma unroll
            for (int w = 0; w < 8; w++) {
                float4 e = red[w * 64 + t];
                float ob1 = e.x, ob2 = e.y;
                int   oi1 = __float_as_int(e.z);
                if (ob1 > bb1 || (ob1 == bb1 && oi1 < bi)) {
                    bb2 = fmaxf(bb1, ob2); bb1 = ob1; bi = oi1;
                } else {
                    bb2 = fmaxf(bb2, ob1);
                }
            }
            g_part[(size_t)(base + t) * REF_SLICES + slice] =
                make_float4(bb1, bb2, __int_as_float(bi), 0.f);
        }
    }
}

// ---------------------------------------------------------------------------
// Kernel 7: merge2 — refine2 slices -> token or exact list
// ---------------------------------------------------------------------------
__global__ void __launch_bounds__(256)
merge2_kernel(float* __restrict__ tok_f, int* __restrict__ tok_i) {
    const int i = blockIdx.x * blockDim.x + threadIdx.x;
    if (i >= g_fixcnt2) return;
    float bb1 = -3.4e38f, bb2 = -3.4e38f;
    int   bi  = 0x7FFFFFFF;
    #pragma unroll 4
    for (int s = 0; s < REF_SLICES; s++) {
        float4 e = g_part[(size_t)i * REF_SLICES + s];
        float ob1 = e.x, ob2 = e.y;
        int   oi1 = __float_as_int(e.z);
        if (ob1 > bb1 || (ob1 == bb1 && oi1 < bi)) {
            bb2 = fmaxf(bb1, ob2); bb1 = ob1; bi = oi1;
        } else {
            bb2 = fmaxf(bb2, ob1);
        }
    }
    const int row = g_fixlist2[i];
    if (bb1 - bb2 < TH_GAP3) {
        int pos = atomicAdd(&g_fixcnt3, 1);
        g_fixlist3[pos] = row;
        g_keys[pos]     = 0ULL;
    } else {
        if (tok_f) tok_f[row] = (float)bi;
        if (tok_i) tok_i[row] = bi;
    }
}

// ---------------------------------------------------------------------------
// Kernel 8: exact fp32 rescore for deep-tie rows (tiny cnt3)
// ---------------------------------------------------------------------------
__global__ void __launch_bounds__(128)
fixup_score_kernel(const float* __restrict__ vocab) {
    __shared__ float4             xs[FIX_RPG][KDIM / 4];
    __shared__ unsigned long long skey[FIX_RPG][128];
    const int t    = threadIdx.x;
    const int cnt  = g_fixcnt3;
    const int slab = blockIdx.x & (FIX_SLABS - 1);
    const int v0   = slab * FIX_VSLAB;
    const int v    = v0 + t;

    for (int rg = blockIdx.x >> 5; rg * FIX_RPG < cnt; rg += FIX_GROUPS) {
        const int base = rg * FIX_RPG;
        const int nr   = min(FIX_RPG, cnt - base);
        __syncthreads();
        for (int i = t; i < nr * (KDIM / 4); i += 128) {
            int r = i >> 6, k4 = i & 63;
            xs[r][k4] = *(const float4*)(g_patches
                        + (size_t)g_fixlist3[base + r] * KDIM + k4 * 4);
        }
        __syncthreads();

        const float4* vr = (const float4*)(vocab + (size_t)v * KDIM);
        float acc[FIX_RPG];
        #pragma unroll
        for (int r = 0; r < FIX_RPG; r++) acc[r] = 0.f;
        #pragma unroll 4
        for (int k = 0; k < KDIM / 4; k++) {
            const float4 q = vr[k];
            #pragma unroll
            for (int r = 0; r < FIX_RPG; r++) {
                const float4 x = xs[r][k];
                acc[r] = fmaf(x.x, q.x, acc[r]);
                acc[r] = fmaf(x.y, q.y, acc[r]);
                acc[r] = fmaf(x.z, q.z, acc[r]);
                acc[r] = fmaf(x.w, q.w, acc[r]);
            }
        }
        const float h = g_nhv2[v];
        #pragma unroll
        for (int r = 0; r < FIX_RPG; r++) skey[r][t] = mkkey(acc[r] + h, v);
        __syncthreads();

        const int w = t >> 5, lane = t & 31;
        #pragma unroll
        for (int hh = 0; hh < 2; hh++) {
            const int r = 2 * w + hh;
            if (r < nr) {
                unsigned long long k = skey[r][lane];
                k = max(k, skey[r][lane + 32]);
                k = max(k, skey[r][lane + 64]);
                k = max(k, skey[r][lane + 96]);
                #pragma unroll
                for (int off = 16; off; off >>= 1) {
                    unsigned long long ok = __shfl_xor_sync(0xFFFFFFFFu, k, off);
                    if (ok > k) k = ok;
                }
                if (lane == 0) atomicMax(&g_keys[base + r], k);
            }
        }
    }
}

// ---------------------------------------------------------------------------
// Kernel 9: decode exact keys -> tokens
// ---------------------------------------------------------------------------
__global__ void __launch_bounds__(256)
fixup_write_kernel(float* __restrict__ tok_f, int* __restrict__ tok_i) {
    const int i = blockIdx.x * blockDim.x + threadIdx.x;
    if (i >= g_fixcnt3) return;
    const int row = g_fixlist3[i];
    const int idx = (int)(~(uint32_t)(g_keys[i] & 0xFFFFFFFFull));
    if (tok_f) tok_f[row] = (float)idx;
    if (tok_i) tok_i[row] = idx;
}

// ---------------------------------------------------------------------------
extern "C" void kernel_launch(void* const* d_in, const int* in_sizes, int n_in,
                              void* d_out, int out_size) {
    const float* images = (const float*)d_in[0];
    const float* vocab  = (const float*)d_in[1];

    float* out       = (float*)d_out;
    float* patch_out = nullptr;
    float* tok_f     = nullptr;
    int*   tok_i     = nullptr;
    if (out_size >= N_PATCH_ELEMS + N_TOKENS) {
        patch_out = out;
        tok_f     = out + N_PATCH_ELEMS;
    } else if (out_size == N_PATCH_ELEMS) {
        patch_out = out;
    } else {
        tok_i = (int*)d_out;
    }

    cudaFuncSetAttribute(gemm_imma_kernel,
                         cudaFuncAttributeMaxDynamicSharedMemorySize, SMEM_BYTES);
    cudaFuncSetAttribute(refine1_kernel,
                         cudaFuncAttributeMaxDynamicSharedMemorySize, R1SMEM);
    cudaFuncSetAttribute(refine2_kernel,
                         cudaFuncAttributeMaxDynamicSharedMemorySize, RSMEM);

    patchify_kernel<<<(N_PATCH_ELEMS / 4 + 255) / 256, 256>>>(images, patch_out);
    patch_quant_kernel<<<ROWS / 8, 256>>>();
    vocab_prep_kernel<<<(VROWS * 32 + 255) / 256, 256>>>(vocab);
    vocab_quant_kernel<<<VROWS / 8, 256>>>(vocab);
    gemm_imma_kernel<<<ROWS / M_CTA, NTHR, SMEM_BYTES>>>(tok_f, tok_i);
    refine1_kernel<<<REF1_GRID, 256, R1SMEM>>>();
    merge1_kernel<<<ROWS / 256, 256>>>(tok_f, tok_i);
    refine2_kernel<<<REF2_GRID, 256, RSMEM>>>();
    merge2_kernel<<<ROWS / 256, 256>>>(tok_f, tok_i);
    fixup_score_kernel<<<FIX_GRID, 128>>>(vocab);
    fixup_write_kernel<<<ROWS / 256, 256>>>(tok_f, tok_i);
}

// round 14
// speedup vs baseline: 2.2107x; 2.2107x over previous
#include <cuda_runtime.h>
#include <cuda_fp16.h>
#include <cstdint>

// ---------------- problem shapes ----------------
#define B_IMG   64
#define H_IMG   256
#define W_IMG   256
#define PATCH   16
#define ROWS    16384
#define VROWS   4096
#define KDIM    256
#define N_PATCH_ELEMS (ROWS * KDIM)
#define N_TOKENS      ROWS

// ---------------- main GEMM tiling (R11 proven) ----------------
#define M_CTA   128
#define N_TILE  256
#define NT_COUNT (VROWS / N_TILE)          // 16
#define NCHUNKS (NT_COUNT * 4)             // 64  (K chunks of 64)
#define NTHR    512
#define TH_GAP  0.05f

// ---------------- refine (3-term fp16 split, M-tile = 32) ----------------
#define REF_SLICES  32
#define REF_VS      (VROWS / REF_SLICES)    // 128
#define REF_MGRP    16
#define REF_GRID    (REF_MGRP * REF_SLICES) // 512
#define TH_GAP2     0.0015f
// refine SMEM (bytes)
#define RA_HI   0            // 4 panels x 4KB (32 rows x 128B)
#define RA_LO   16384
#define RB_HI   32768        // 128 rows x 128B
#define RB_LO   49152
#define RRED    65536        // 8 warps x 32 rows x 16B
#define RSMEM   69632

// ---------------- exact fixup geometry ----------------
#define FIX_SLABS   32
#define FIX_VSLAB   (VROWS / FIX_SLABS)     // 128
#define FIX_RPG     8
#define FIX_GROUPS  64
#define FIX_GRID    (FIX_SLABS * FIX_GROUPS)

// ---------------- main GEMM SMEM ----------------
#define SM_A    0
#define SM_B    65536
#define SM_NHV  131072
#define SMEM_BYTES 147456

// ---------------- device scratch ----------------
__device__ float              g_patches[N_PATCH_ELEMS];
__device__ __half             g_ph[N_PATCH_ELEMS];
__device__ __half             g_plo[N_PATCH_ELEMS];
__device__ __half             g_vh[VROWS * KDIM];
__device__ __half             g_vlo[VROWS * KDIM];
__device__ float              g_nhv2[VROWS];          // -0.5*||v||^2
__device__ int                g_fixcnt, g_fixcnt2;
__device__ int                g_fixlist[ROWS];
__device__ int                g_fixlist2[ROWS];
__device__ unsigned long long g_keys[ROWS];
__device__ float4             g_part[ROWS * REF_SLICES];

// ---------------- helpers ----------------
__device__ __forceinline__ uint32_t smem_u32(const void* p) {
    uint32_t a;
    asm("{ .reg .u64 t; cvta.to.shared.u64 t, %1; cvt.u32.u64 %0, t; }" : "=r"(a) : "l"(p));
    return a;
}
#define SMEM_SWZ(off) ((uint32_t)(off) ^ (((uint32_t)(off) >> 3) & 0x70u))

__device__ __forceinline__ void ldm4(uint32_t* r, uint32_t addr) {
    asm volatile("ldmatrix.sync.aligned.m8n8.x4.shared.b16 {%0,%1,%2,%3}, [%4];"
        : "=r"(r[0]), "=r"(r[1]), "=r"(r[2]), "=r"(r[3]) : "r"(addr));
}
__device__ __forceinline__ void mma_f16(float* c, const uint32_t* a, uint32_t b0, uint32_t b1) {
    asm volatile("mma.sync.aligned.m16n8k16.row.col.f32.f16.f16.f32 "
        "{%0,%1,%2,%3}, {%4,%5,%6,%7}, {%8,%9}, {%0,%1,%2,%3};"
        : "+f"(c[0]), "+f"(c[1]), "+f"(c[2]), "+f"(c[3])
        : "r"(a[0]), "r"(a[1]), "r"(a[2]), "r"(a[3]), "r"(b0), "r"(b1));
}
#define CP16(dst, src)  asm volatile("cp.async.cg.shared.global [%0], [%1], 16;" :: "r"(dst), "l"(src))
#define CP_COMMIT()     asm volatile("cp.async.commit_group;" ::: "memory")
#define CP_WAIT(n)      asm volatile("cp.async.wait_group %0;" :: "n"(n) : "memory")

__device__ __forceinline__ uint32_t pack2h(__half a, __half b) {
    return (uint32_t)__half_as_ushort(a) | ((uint32_t)__half_as_ushort(b) << 16);
}
__device__ __forceinline__ uint32_t ford(float s) {
    uint32_t b = __float_as_uint(s);
    return (b & 0x80000000u) ? ~b : (b | 0x80000000u);
}
__device__ __forceinline__ unsigned long long mkkey(float s, int idx) {
    return ((unsigned long long)ford(s) << 32) | (uint32_t)(~(uint32_t)idx);
}

// ---------------------------------------------------------------------------
// Kernel 1: patchify + fp16 hi/lo split (+ counter reset)
// ---------------------------------------------------------------------------
__global__ void patchify_kernel(const float* __restrict__ img,
                                float* __restrict__ out_opt) {
    int i = blockIdx.x * blockDim.x + threadIdx.x;
    if (blockIdx.x == 0 && threadIdx.x == 0) { g_fixcnt = 0; g_fixcnt2 = 0; }
    if (i >= N_PATCH_ELEMS / 4) return;
    int f  = i << 2;
    int d  = f & 255;
    int pn = f >> 8;
    int b  = pn >> 8;
    int n  = pn & 255;
    int r  = d >> 4, c = d & 15;
    int py = n >> 4, px = n & 15;
    const float4 v = *(const float4*)(img + (size_t)b * (H_IMG * W_IMG)
                                      + (size_t)(py * PATCH + r) * W_IMG + px * PATCH + c);
    ((float4*)g_patches)[i] = v;
    if (out_opt) ((float4*)out_opt)[i] = v;
    float x[4] = {v.x, v.y, v.z, v.w};
    __half hi[4], lo[4];
    #pragma unroll
    for (int j = 0; j < 4; j++) {
        hi[j] = __float2half_rn(x[j]);
        lo[j] = __float2half_rn(x[j] - __half2float(hi[j]));
    }
    uint2 ph, pl;
    ph.x = pack2h(hi[0], hi[1]); ph.y = pack2h(hi[2], hi[3]);
    pl.x = pack2h(lo[0], lo[1]); pl.y = pack2h(lo[2], lo[3]);
    ((uint2*)g_ph)[i]  = ph;
    ((uint2*)g_plo)[i] = pl;
}

// ---------------------------------------------------------------------------
// Kernel 2: vocab prep — -0.5||v||^2 + fp16 hi/lo split (1 warp / row)
// ---------------------------------------------------------------------------
__global__ void vocab_prep_kernel(const float* __restrict__ vocab) {
    int gt   = blockIdx.x * blockDim.x + threadIdx.x;
    int w    = gt >> 5;
    int lane = gt & 31;
    if (w >= VROWS) return;
    float s = 0.f;
    #pragma unroll
    for (int j = 0; j < 2; j++) {
        int e = lane * 4 + j * 128;
        float4 q = *(const float4*)(vocab + (size_t)w * KDIM + e);
        s += q.x * q.x + q.y * q.y + q.z * q.z + q.w * q.w;
        float x[4] = {q.x, q.y, q.z, q.w};
        __half hi[4], lo[4];
        #pragma unroll
        for (int t = 0; t < 4; t++) {
            hi[t] = __float2half_rn(x[t]);
            lo[t] = __float2half_rn(x[t] - __half2float(hi[t]));
        }
        uint2 ph, pl;
        ph.x = pack2h(hi[0], hi[1]); ph.y = pack2h(hi[2], hi[3]);
        pl.x = pack2h(lo[0], lo[1]); pl.y = pack2h(lo[2], lo[3]);
        *(uint2*)(g_vh  + (size_t)w * KDIM + e) = ph;
        *(uint2*)(g_vlo + (size_t)w * KDIM + e) = pl;
    }
    #pragma unroll
    for (int off = 16; off; off >>= 1) s += __shfl_xor_sync(0xFFFFFFFFu, s, off);
    if (lane == 0) g_nhv2[w] = -0.5f * s;
}

// ---------------------------------------------------------------------------
// Kernel 3: main fp16 mma.sync GEMM + fused top-2 argmax (R11, verbatim)
// ---------------------------------------------------------------------------
__global__ void __launch_bounds__(NTHR, 1)
gemm_mma_kernel(float* __restrict__ tok_f, int* __restrict__ tok_i) {
    extern __shared__ char smem[];
    const uint32_t sb = smem_u32(smem);
    const int t    = threadIdx.x;
    const int wid  = t >> 5;
    const int lane = t & 31;
    const int wm   = wid >> 3;
    const int wn   = wid & 7;
    const int grp  = lane >> 2;
    const int tig  = lane & 3;
    const int m0   = blockIdx.x * M_CTA;

    for (int i = t; i < VROWS / 4; i += NTHR)
        ((float4*)(smem + SM_NHV))[i] = ((const float4*)g_nhv2)[i];

    #pragma unroll
    for (int i = 0; i < 8; i++) {
        int f = t + i * NTHR;
        int m = f >> 5;
        int c = f & 31;
        int panel = c >> 3;
        int q = c & 7;
        uint32_t dst = SMEM_SWZ(m * 128 + q * 16);
        *(uint4*)(smem + SM_A + panel * 16384 + dst) =
            *(const uint4*)(g_ph + (size_t)(m0 + m) * KDIM + c * 8);
    }
    __syncthreads();

    #pragma unroll
    for (int i = 0; i < 4; i++) {
        int f = t + i * NTHR;
        int r = f >> 3, q = f & 7;
        uint32_t dst = sb + SM_B + SMEM_SWZ(r * 128 + q * 16);
        CP16(dst, g_vh + (size_t)r * KDIM + q * 8);
    }
    CP_COMMIT();

    float acc[4][4][4];
    #pragma unroll
    for (int a = 0; a < 4; a++)
        #pragma unroll
        for (int b = 0; b < 4; b++)
            #pragma unroll
            for (int c = 0; c < 4; c++) acc[a][b][c] = 0.f;

    float b1v[8], b2v[8];
    int   i1v[8];
    #pragma unroll
    for (int r = 0; r < 8; r++) { b1v[r] = -3.4e38f; b2v[r] = -3.4e38f; i1v[r] = 0; }

    const float* nhv = (const float*)(smem + SM_NHV);

    for (int gch = 0; gch < NCHUNKS; gch++) {
        const int nt  = gch >> 2;
        const int kc  = gch & 3;
        const int buf = gch & 1;

        if (gch < NCHUNKS - 1) {
            const int gn  = gch + 1;
            const int nn0 = (gn >> 2) << 8;
            const int nkc = gn & 3;
            const uint32_t bb = sb + SM_B + (gn & 1) * 32768;
            #pragma unroll
            for (int i = 0; i < 4; i++) {
                int f = t + i * NTHR;
                int r = f >> 3, q = f & 7;
                uint32_t dst = bb + SMEM_SWZ(r * 128 + q * 16);
                CP16(dst, g_vh + (size_t)(nn0 + r) * KDIM + nkc * 64 + q * 8);
            }
            CP_COMMIT();
            CP_WAIT(1);
        } else {
            CP_WAIT(0);
        }
        __syncthreads();

        const uint32_t b_base = sb + SM_B + buf * 32768;
        const uint32_t a_base = sb + SM_A + kc * 16384;
        const int rowA = wm * 64 + (lane & 15);
        const int rowB = wn * 32 + (lane & 15);

        #pragma unroll
        for (int ks = 0; ks < 4; ks++) {
            const uint32_t colb = ks * 32 + (lane >> 4) * 16;
            uint32_t ah[4][4], bh[2][4];
            #pragma unroll
            for (int mt = 0; mt < 4; mt++)
                ldm4(ah[mt], a_base + SMEM_SWZ((rowA + mt * 16) * 128 + colb));
            #pragma unroll
            for (int p = 0; p < 2; p++)
                ldm4(bh[p], b_base + SMEM_SWZ((rowB + p * 16) * 128 + colb));
            #pragma unroll
            for (int mt = 0; mt < 4; mt++) {
                #pragma unroll
                for (int n8 = 0; n8 < 4; n8++) {
                    const int p = n8 >> 1, w = n8 & 1;
                    mma_f16(acc[mt][n8], ah[mt],
                            w ? bh[p][1] : bh[p][0],
                            w ? bh[p][3] : bh[p][2]);
                }
            }
        }
        __syncthreads();

        if (kc == 3) {
            #pragma unroll
            for (int mt = 0; mt < 4; mt++) {
                #pragma unroll
                for (int n8 = 0; n8 < 4; n8++) {
                    const int cb = nt * N_TILE + wn * 32 + n8 * 8 + tig * 2;
                    const float2 h = *(const float2*)(nhv + cb);
                    const float s00 = acc[mt][n8][0] + h.x;
                    const float s01 = acc[mt][n8][1] + h.y;
                    const float s10 = acc[mt][n8][2] + h.x;
                    const float s11 = acc[mt][n8][3] + h.y;
                    const int r0 = mt * 2, r1 = mt * 2 + 1;
                    if (s00 > b1v[r0]) { b2v[r0] = b1v[r0]; b1v[r0] = s00; i1v[r0] = cb; }
                    else if (s00 > b2v[r0]) b2v[r0] = s00;
                    if (s01 > b1v[r0]) { b2v[r0] = b1v[r0]; b1v[r0] = s01; i1v[r0] = cb + 1; }
                    else if (s01 > b2v[r0]) b2v[r0] = s01;
                    if (s10 > b1v[r1]) { b2v[r1] = b1v[r1]; b1v[r1] = s10; i1v[r1] = cb; }
                    else if (s10 > b2v[r1]) b2v[r1] = s10;
                    if (s11 > b1v[r1]) { b2v[r1] = b1v[r1]; b1v[r1] = s11; i1v[r1] = cb + 1; }
                    else if (s11 > b2v[r1]) b2v[r1] = s11;
                    acc[mt][n8][0] = 0.f; acc[mt][n8][1] = 0.f;
                    acc[mt][n8][2] = 0.f; acc[mt][n8][3] = 0.f;
                }
            }
        }
    }

    #pragma unroll
    for (int d = 1; d <= 2; d <<= 1) {
        #pragma unroll
        for (int r = 0; r < 8; r++) {
            float ob1 = __shfl_xor_sync(0xFFFFFFFFu, b1v[r], d);
            float ob2 = __shfl_xor_sync(0xFFFFFFFFu, b2v[r], d);
            int   oi1 = __shfl_xor_sync(0xFFFFFFFFu, i1v[r], d);
            if (ob1 > b1v[r] || (ob1 == b1v[r] && oi1 < i1v[r])) {
                b2v[r] = fmaxf(b1v[r], ob2);
                b1v[r] = ob1; i1v[r] = oi1;
            } else {
                b2v[r] = fmaxf(b2v[r], ob1);
            }
        }
    }

    __syncthreads();
    float4* red = (float4*)(smem + SM_B);
    if (tig == 0) {
        #pragma unroll
        for (int mt = 0; mt < 4; mt++) {
            #pragma unroll
            for (int h = 0; h < 2; h++) {
                const int rl = wm * 64 + mt * 16 + grp + h * 8;
                const int r  = mt * 2 + h;
                red[wn * 128 + rl] = make_float4(b1v[r], b2v[r], __int_as_float(i1v[r]), 0.f);
            }
        }
    }
    __syncthreads();
    if (t < M_CTA) {
        float bb1 = -3.4e38f, bb2 = -3.4e38f;
        int   bi  = 0x7FFFFFFF;
        #pragma unroll
        for (int w = 0; w < 8; w++) {
            float4 e = red[w * 128 + t];
            float ob1 = e.x, ob2 = e.y;
            int   oi1 = __float_as_int(e.z);
            if (ob1 > bb1 || (ob1 == bb1 && oi1 < bi)) {
                bb2 = fmaxf(bb1, ob2); bb1 = ob1; bi = oi1;
            } else {
                bb2 = fmaxf(bb2, ob1);
            }
        }
        const int row = m0 + t;
        if (tok_f) tok_f[row] = (float)bi;
        if (tok_i) tok_i[row] = bi;
        if (bb1 - bb2 < TH_GAP) {
            int pos = atomicAdd(&g_fixcnt, 1);
            g_fixlist[pos] = row;
        }
    }
}

// ---------------------------------------------------------------------------
// Kernel 4: refine — 3-term fp16-split HMMA rescore; M-tile=32, VS=128.
// grid = 16 m-groups x 32 slices. 256 thr (8 warps x 16 N-cols).
// ---------------------------------------------------------------------------
__global__ void __launch_bounds__(256, 1)
refine_kernel() {
    extern __shared__ char smem[];
    const uint32_t sb = smem_u32(smem);
    const int cnt = g_fixcnt;
    if (cnt == 0) return;
    const int t     = threadIdx.x;
    const int wn    = t >> 5;
    const int lane  = t & 31;
    const int grp   = lane >> 2;
    const int tig   = lane & 3;
    const int slice = blockIdx.x & (REF_SLICES - 1);
    const int n0    = slice * REF_VS;

    for (int mt32 = blockIdx.x >> 5; mt32 * 32 < cnt; mt32 += REF_MGRP) {
        const int base = mt32 * 32;
        __syncthreads();
        // gather A hi/lo (32 rows x 256 K), clamp padded rows. 1024 uint4.
        for (int i = t; i < 1024; i += 256) {
            int r = i >> 5, c = i & 31;
            int panel = c >> 3, q = c & 7;
            int slot = base + r;
            int grow = g_fixlist[slot < cnt ? slot : base];
            uint32_t dst = panel * 4096 + SMEM_SWZ(r * 128 + q * 16);
            *(uint4*)(smem + RA_HI + dst) = *(const uint4*)(g_ph  + (size_t)grow * KDIM + c * 8);
            *(uint4*)(smem + RA_LO + dst) = *(const uint4*)(g_plo + (size_t)grow * KDIM + c * 8);
        }
        __syncthreads();

        float acc[2][2][4];
        #pragma unroll
        for (int a = 0; a < 2; a++)
            #pragma unroll
            for (int b = 0; b < 2; b++)
                #pragma unroll
                for (int c = 0; c < 4; c++) acc[a][b][c] = 0.f;

        for (int kc = 0; kc < 4; kc++) {
            __syncthreads();
            // load B hi/lo chunk: 128 rows x 64 K
            for (int i = t; i < 1024; i += 256) {
                int r = i >> 3, q = i & 7;
                uint32_t dst = SMEM_SWZ(r * 128 + q * 16);
                size_t src = (size_t)(n0 + r) * KDIM + kc * 64 + q * 8;
                *(uint4*)(smem + RB_HI + dst) = *(const uint4*)(g_vh  + src);
                *(uint4*)(smem + RB_LO + dst) = *(const uint4*)(g_vlo + src);
            }
            __syncthreads();

            const uint32_t ahb = sb + RA_HI + kc * 4096;
            const uint32_t alb = sb + RA_LO + kc * 4096;
            const int rowA = lane & 15;
            const int rowB = wn * 16 + (lane & 15);
            #pragma unroll
            for (int ks = 0; ks < 4; ks++) {
                const uint32_t colb = ks * 32 + (lane >> 4) * 16;
                uint32_t ahi[2][4], alo[2][4], bhi[4], blo[4];
                #pragma unroll
                for (int mt = 0; mt < 2; mt++) {
                    ldm4(ahi[mt], ahb + SMEM_SWZ((rowA + mt * 16) * 128 + colb));
                    ldm4(alo[mt], alb + SMEM_SWZ((rowA + mt * 16) * 128 + colb));
                }
                ldm4(bhi, sb + RB_HI + SMEM_SWZ(rowB * 128 + colb));
                ldm4(blo, sb + RB_LO + SMEM_SWZ(rowB * 128 + colb));
                #pragma unroll
                for (int mt = 0; mt < 2; mt++) {
                    #pragma unroll
                    for (int n8 = 0; n8 < 2; n8++) {
                        const uint32_t h0 = n8 ? bhi[1] : bhi[0];
                        const uint32_t h1 = n8 ? bhi[3] : bhi[2];
                        const uint32_t l0 = n8 ? blo[1] : blo[0];
                        const uint32_t l1 = n8 ? blo[3] : blo[2];
                        mma_f16(acc[mt][n8], ahi[mt], h0, h1);
                        mma_f16(acc[mt][n8], ahi[mt], l0, l1);
                        mma_f16(acc[mt][n8], alo[mt], h0, h1);
                    }
                }
            }
        }

        // per-row top-2 over this 128-vocab slice (4 rows per thread)
        float b1v[4], b2v[4];
        int   i1v[4];
        #pragma unroll
        for (int r = 0; r < 4; r++) { b1v[r] = -3.4e38f; b2v[r] = -3.4e38f; i1v[r] = 0; }
        #pragma unroll
        for (int mt = 0; mt < 2; mt++) {
            #pragma unroll
            for (int n8 = 0; n8 < 2; n8++) {
                const int cb = n0 + wn * 16 + n8 * 8 + tig * 2;
                const float hx = g_nhv2[cb], hy = g_nhv2[cb + 1];
                const float s00 = acc[mt][n8][0] + hx;
                const float s01 = acc[mt][n8][1] + hy;
                const float s10 = acc[mt][n8][2] + hx;
                const float s11 = acc[mt][n8][3] + hy;
                const int r0 = mt * 2, r1 = mt * 2 + 1;
                if (s00 > b1v[r0]) { b2v[r0] = b1v[r0]; b1v[r0] = s00; i1v[r0] = cb; }
                else if (s00 > b2v[r0]) b2v[r0] = s00;
                if (s01 > b1v[r0]) { b2v[r0] = b1v[r0]; b1v[r0] = s01; i1v[r0] = cb + 1; }
                else if (s01 > b2v[r0]) b2v[r0] = s01;
                if (s10 > b1v[r1]) { b2v[r1] = b1v[r1]; b1v[r1] = s10; i1v[r1] = cb; }
                else if (s10 > b2v[r1]) b2v[r1] = s10;
                if (s11 > b1v[r1]) { b2v[r1] = b1v[r1]; b1v[r1] = s11; i1v[r1] = cb + 1; }
                else if (s11 > b2v[r1]) b2v[r1] = s11;
            }
        }
        #pragma unroll
        for (int d = 1; d <= 2; d <<= 1) {
            #pragma unroll
            for (int r = 0; r < 4; r++) {
                float ob1 = __shfl_xor_sync(0xFFFFFFFFu, b1v[r], d);
                float ob2 = __shfl_xor_sync(0xFFFFFFFFu, b2v[r], d);
                int   oi1 = __shfl_xor_sync(0xFFFFFFFFu, i1v[r], d);
                if (ob1 > b1v[r] || (ob1 == b1v[r] && oi1 < i1v[r])) {
                    b2v[r] = fmaxf(b1v[r], ob2);
                    b1v[r] = ob1; i1v[r] = oi1;
                } else {
                    b2v[r] = fmaxf(b2v[r], ob1);
                }
            }
        }
        __syncthreads();
        float4* red = (float4*)(smem + RRED);
        if (tig == 0) {
            #pragma unroll
            for (int mt = 0; mt < 2; mt++) {
                #pragma unroll
                for (int h = 0; h < 2; h++) {
                    const int rl = mt * 16 + grp + h * 8;
                    const int r  = mt * 2 + h;
                    red[wn * 32 + rl] = make_float4(b1v[r], b2v[r], __int_as_float(i1v[r]), 0.f);
                }
            }
        }
        __syncthreads();
        if (t < 32) {
            float bb1 = -3.4e38f, bb2 = -3.4e38f;
            int   bi  = 0x7FFFFFFF;
            #pragma unroll
            for (int w = 0; w < 8; w++) {
                float4 e = red[w * 32 + t];
                float ob1 = e.x, ob2 = e.y;
                int   oi1 = __float_as_int(e.z);
                if (ob1 > bb1 || (ob1 == bb1 && oi1 < bi)) {
                    bb2 = fmaxf(bb1, ob2); bb1 = ob1; bi = oi1;
                } else {
                    bb2 = fmaxf(bb2, ob1);
                }
            }
            g_part[(size_t)(base + t) * REF_SLICES + slice] =
                make_float4(bb1, bb2, __int_as_float(bi), 0.f);
        }
    }
}

// ---------------------------------------------------------------------------
// Kernel 5: merge refine slices -> final tokens or exact-rescore list
// ---------------------------------------------------------------------------
__global__ void __launch_bounds__(256)
merge_kernel(float* __restrict__ tok_f, int* __restrict__ tok_i) {
    const int i = blockIdx.x * blockDim.x + threadIdx.x;
    if (i >= g_fixcnt) return;
    float bb1 = -3.4e38f, bb2 = -3.4e38f;
    int   bi  = 0x7FFFFFFF;
    #pragma unroll 4
    for (int s = 0; s < REF_SLICES; s++) {
        float4 e = g_part[(size_t)i * REF_SLICES + s];
        float ob1 = e.x, ob2 = e.y;
        int   oi1 = __float_as_int(e.z);
        if (ob1 > bb1 || (ob1 == bb1 && oi1 < bi)) {
            bb2 = fmaxf(bb1, ob2); bb1 = ob1; bi = oi1;
        } else {
            bb2 = fmaxf(bb2, ob1);
        }
    }
    const int row = g_fixlist[i];
    if (bb1 - bb2 < TH_GAP2) {
        int pos = atomicAdd(&g_fixcnt2, 1);
        g_fixlist2[pos] = row;
        g_keys[pos]     = 0ULL;
    } else {
        if (tok_f) tok_f[row] = (float)bi;
        if (tok_i) tok_i[row] = bi;
    }
}

// ---------------------------------------------------------------------------
// Kernel 6: exact fp32 rescore for deep-tie rows (tiny cnt2)
// ---------------------------------------------------------------------------
__global__ void __launch_bounds__(128)
fixup_score_kernel(const float* __restrict__ vocab) {
    __shared__ float4             xs[FIX_RPG][KDIM / 4];
    __shared__ unsigned long long skey[FIX_RPG][128];
    const int t    = threadIdx.x;
    const int cnt  = g_fixcnt2;
    const int slab = blockIdx.x & (FIX_SLABS - 1);
    const int v0   = slab * FIX_VSLAB;
    const int v    = v0 + t;

    for (int rg = blockIdx.x >> 5; rg * FIX_RPG < cnt; rg += FIX_GROUPS) {
        const int base = rg * FIX_RPG;
        const int nr   = min(FIX_RPG, cnt - base);
        __syncthreads();
        for (int i = t; i < nr * (KDIM / 4); i += 128) {
            int r = i >> 6, k4 = i & 63;
            xs[r][k4] = *(const float4*)(g_patches
                        + (size_t)g_fixlist2[base + r] * KDIM + k4 * 4);
        }
        __syncthreads();

        const float4* vr = (const float4*)(vocab + (size_t)v * KDIM);
        float acc[FIX_RPG];
        #pragma unroll
        for (int r = 0; r < FIX_RPG; r++) acc[r] = 0.f;
        #pragma unroll 4
        for (int k = 0; k < KDIM / 4; k++) {
            const float4 q = vr[k];
            #pragma unroll
            for (int r = 0; r < FIX_RPG; r++) {
                const float4 x = xs[r][k];
                acc[r] = fmaf(x.x, q.x, acc[r]);
                acc[r] = fmaf(x.y, q.y, acc[r]);
                acc[r] = fmaf(x.z, q.z, acc[r]);
                acc[r] = fmaf(x.w, q.w, acc[r]);
            }
        }
        const float h = g_nhv2[v];
        #pragma unroll
        for (int r = 0; r < FIX_RPG; r++) skey[r][t] = mkkey(acc[r] + h, v);
        __syncthreads();

        const int w = t >> 5, lane = t & 31;
        #pragma unroll
        for (int hh = 0; hh < 2; hh++) {
            const int r = 2 * w + hh;
            if (r < nr) {
                unsigned long long k = skey[r][lane];
                k = max(k, skey[r][lane + 32]);
                k = max(k, skey[r][lane + 64]);
                k = max(k, skey[r][lane + 96]);
                #pragma unroll
                for (int off = 16; off; off >>= 1) {
                    unsigned long long ok = __shfl_xor_sync(0xFFFFFFFFu, k, off);
                    if (ok > k) k = ok;
                }
                if (lane == 0) atomicMax(&g_keys[base + r], k);
            }
        }
    }
}

// ---------------------------------------------------------------------------
// Kernel 7: decode exact keys -> tokens
// ---------------------------------------------------------------------------
__global__ void __launch_bounds__(256)
fixup_write_kernel(float* __restrict__ tok_f, int* __restrict__ tok_i) {
    const int i = blockIdx.x * blockDim.x + threadIdx.x;
    if (i >= g_fixcnt2) return;
    const int row = g_fixlist2[i];
    const int idx = (int)(~(uint32_t)(g_keys[i] & 0xFFFFFFFFull));
    if (tok_f) tok_f[row] = (float)idx;
    if (tok_i) tok_i[row] = idx;
}

// ---------------------------------------------------------------------------
extern "C" void kernel_launch(void* const* d_in, const int* in_sizes, int n_in,
                              void* d_out, int out_size) {
    const float* images = (const float*)d_in[0];
    const float* vocab  = (const float*)d_in[1];

    float* out       = (float*)d_out;
    float* patch_out = nullptr;
    float* tok_f     = nullptr;
    int*   tok_i     = nullptr;
    if (out_size >= N_PATCH_ELEMS + N_TOKENS) {
        patch_out = out;
        tok_f     = out + N_PATCH_ELEMS;
    } else if (out_size == N_PATCH_ELEMS) {
        patch_out = out;
    } else {
        tok_i = (int*)d_out;
    }

    cudaFuncSetAttribute(gemm_mma_kernel,
                         cudaFuncAttributeMaxDynamicSharedMemorySize, SMEM_BYTES);
    cudaFuncSetAttribute(refine_kernel,
                         cudaFuncAttributeMaxDynamicSharedMemorySize, RSMEM);

    patchify_kernel<<<(N_PATCH_ELEMS / 4 + 255) / 256, 256>>>(images, patch_out);
    vocab_prep_kernel<<<(VROWS * 32 + 255) / 256, 256>>>(vocab);
    gemm_mma_kernel<<<ROWS / M_CTA, NTHR, SMEM_BYTES>>>(tok_f, tok_i);
    refine_kernel<<<REF_GRID, 256, RSMEM>>>();
    merge_kernel<<<ROWS / 256, 256>>>(tok_f, tok_i);
    fixup_score_kernel<<<FIX_GRID, 128>>>(vocab);
    fixup_write_kernel<<<ROWS / 256, 256>>>(tok_f, tok_i);
}